// round 10
// baseline (speedup 1.0000x reference)
#include <cuda_runtime.h>
#include <cuda_bf16.h>
#include <math.h>
#include <cstdint>

#define TT 128
#define BB 256
#define DIN 512
#define H1 1024
#define H2 1024
#define H3 512

typedef __nv_bfloat16 bf16;

// ---------------- persistent device storage ---------------------------------
__device__ bf16 g_x_hi[TT * BB * DIN];
__device__ bf16 g_x_lo[TT * BB * DIN];

__device__ bf16 g_W1i_hi[4 * H1 * DIN], g_W1i_lo[4 * H1 * DIN];
__device__ bf16 g_W1h_hi[4 * H1 * H1],  g_W1h_lo[4 * H1 * H1];
__device__ bf16 g_W2i_hi[4 * H2 * H1],  g_W2i_lo[4 * H2 * H1];
__device__ bf16 g_W2h_hi[4 * H2 * H2],  g_W2h_lo[4 * H2 * H2];
__device__ bf16 g_W3i_hi[4 * H3 * H2],  g_W3i_lo[4 * H3 * H2];
__device__ bf16 g_W3h_hi[4 * H3 * H3],  g_W3h_lo[4 * H3 * H3];

__device__ bf16 g_h1_hi[2][BB * H1], g_h1_lo[2][BB * H1];
__device__ bf16 g_h2_hi[2][BB * H2], g_h2_lo[2][BB * H2];
__device__ bf16 g_h3_hi[2][BB * H3], g_h3_lo[2][BB * H3];

__device__ float g_c1[BB * H1], g_c2[BB * H2], g_c3[BB * H3];

// scheduler state
__device__ int g_cursor;
__device__ int g_f1[TT], g_f2[TT], g_f3[TT];

#define JOBS_PER_T 320            // 128 L1 + 128 L2 + 64 L3
#define TOTAL_JOBS (TT * JOBS_PER_T)

// ---------------- helpers ----------------------------------------------------
__device__ __forceinline__ uint32_t smem_u32(const void* p) {
    uint32_t a;
    asm("{ .reg .u64 t; cvta.to.shared.u64 t, %1; cvt.u32.u64 %0, t; }" : "=r"(a) : "l"(p));
    return a;
}
__device__ __forceinline__ void cp16(uint32_t smem, const void* gmem) {
    asm volatile("cp.async.cg.shared.global [%0], [%1], 16;\n" ::"r"(smem), "l"(gmem));
}
#define CP_COMMIT() asm volatile("cp.async.commit_group;\n" ::: "memory")
#define CP_WAIT(n)  asm volatile("cp.async.wait_group %0;\n" ::"n"(n) : "memory")

__device__ __forceinline__ void ldsm4(unsigned* d, uint32_t addr) {
    asm volatile("ldmatrix.sync.aligned.m8n8.x4.shared.b16 {%0,%1,%2,%3}, [%4];"
                 : "=r"(d[0]), "=r"(d[1]), "=r"(d[2]), "=r"(d[3]) : "r"(addr));
}
__device__ __forceinline__ void mma_bf16(float* c, const unsigned* a, unsigned b0, unsigned b1) {
    asm volatile(
        "mma.sync.aligned.m16n8k16.row.col.f32.bf16.bf16.f32 "
        "{%0,%1,%2,%3},{%4,%5,%6,%7},{%8,%9},{%0,%1,%2,%3};\n"
        : "+f"(c[0]), "+f"(c[1]), "+f"(c[2]), "+f"(c[3])
        : "r"(a[0]), "r"(a[1]), "r"(a[2]), "r"(a[3]), "r"(b0), "r"(b1));
}
__device__ __forceinline__ float sigm(float x) { return 1.0f / (1.0f + __expf(-x)); }

// flag sync: release = fence(all threads) + sync + atomicAdd(tid0)
//            acquire = poll(tid0, volatile) + sync + fence
__device__ __forceinline__ void flag_arrive(int* f) {
    __threadfence();
    __syncthreads();
    if (threadIdx.x == 0) atomicAdd(f, 1);
}
__device__ __forceinline__ void flag_wait(int* f, int target) {
    if (threadIdx.x == 0) {
        volatile int* vf = (volatile int*)f;
        while (*vf < target) __nanosleep(64);
    }
    __syncthreads();
    __threadfence();
}

// ---------------------------------------------------------------------------
// One LSTM tile: gates[b0..b0+63, j0..j0+31 (x4 gates)] via 3-term bf16-split
// GEMM with W_hi pairing (phase A: A_hi+A_lo vs W_hi; phase B: A_hi vs W_lo).
// In-register LSTM epilogue. 3-stage cp.async ring. Cross-CTA data via
// cp.async.cg / __ldcg (L2-coherent; no L1D staleness inside the persistent
// kernel).
// ---------------------------------------------------------------------------
#define BM 64
#define PITCH 72
#define A_STG (BM * PITCH)
#define B_STG (128 * PITCH)
#define STG_ELEMS (2 * A_STG + B_STG)
#define DYN_BYTES (3 * STG_ELEMS * 2)   // 110592 bytes

template <int K1, int K2, int HH>
__device__ void lstm_tile(const bf16* __restrict__ Ai_hi, const bf16* __restrict__ Ai_lo,
                          const bf16* __restrict__ Ah_hi, const bf16* __restrict__ Ah_lo,
                          const bf16* __restrict__ Wi_hi, const bf16* __restrict__ Wi_lo,
                          const bf16* __restrict__ Wh_hi, const bf16* __restrict__ Wh_lo,
                          const float* __restrict__ bih, const float* __restrict__ bhh,
                          float* __restrict__ c,
                          bf16* __restrict__ ho_hi, bf16* __restrict__ ho_lo,
                          int j0, int b0, bf16* dyn)
{
    constexpr int KK = K1 + K2;
    constexpr int KKc = KK / 64;       // chunks per phase
    constexpr int NCH2 = 2 * KKc;

    const uint32_t sbase = smem_u32(dyn);
    const int tid = threadIdx.x;
    const int wid = tid >> 5, lane = tid & 31;
    const int wm = wid >> 2, wn = wid & 3;     // m-half (32 rows), j-slice (8)

    float acc[2][4][4];   // [mi][gate][frag]
#pragma unroll
    for (int mi = 0; mi < 2; ++mi)
#pragma unroll
        for (int g = 0; g < 4; ++g)
#pragma unroll
            for (int r = 0; r < 4; ++r) acc[mi][g][r] = 0.0f;

    auto load_stage = [&](int ci, int s) {
        const bool phA = ci < KKc;
        const int kk = (phA ? ci : ci - KKc) * 64;
        const bf16 *Ah, *Al, *W;
        int col, ld;
        if (kk < K1) {
            Ah = Ai_hi; Al = Ai_lo;
            W = phA ? Wi_hi : Wi_lo;
            col = kk; ld = K1;
        } else {
            Ah = Ah_hi; Al = Ah_lo;
            W = phA ? Wh_hi : Wh_lo;
            col = kk - K1; ld = K2;
        }
        const uint32_t a0base = sbase + (uint32_t)(s * STG_ELEMS) * 2;
        const uint32_t a1base = a0base + A_STG * 2;
        const uint32_t bbase  = a0base + 2 * A_STG * 2;
#pragma unroll
        for (int it = 0; it < 2; ++it) {           // A_hi: 64 rows x 8 quads
            const int idx = tid + it * 256;
            const int r = idx >> 3, q = idx & 7;
            cp16(a0base + (uint32_t)(r * PITCH + q * 8) * 2,
                 Ah + (size_t)(b0 + r) * ld + col + q * 8);
        }
        if (phA) {
#pragma unroll
            for (int it = 0; it < 2; ++it) {       // A_lo
                const int idx = tid + it * 256;
                const int r = idx >> 3, q = idx & 7;
                cp16(a1base + (uint32_t)(r * PITCH + q * 8) * 2,
                     Al + (size_t)(b0 + r) * ld + col + q * 8);
            }
        }
#pragma unroll
        for (int it = 0; it < 4; ++it) {           // W: 128 rows (gate*32+jl)
            const int idx = tid + it * 256;
            const int r = idx >> 3, q = idx & 7;
            const int gate = r >> 5, jl = r & 31;
            cp16(bbase + (uint32_t)(r * PITCH + q * 8) * 2,
                 W + (size_t)(gate * HH + j0 + jl) * ld + col + q * 8);
        }
        CP_COMMIT();
    };

    const int arow_off = lane & 15, acol_off = (lane >> 4) << 3;
    const int b_gsel = (lane >> 3) & 1;
    const int b_kadd = (lane >> 4) << 3;
    const int b_jrow = wn * 8 + (lane & 7);

    auto compute = [&](int ci, int s) {
        const bool phA = ci < KKc;
        const uint32_t a0base = sbase + (uint32_t)(s * STG_ELEMS) * 2;
        const uint32_t a1base = a0base + A_STG * 2;
        const uint32_t bbase  = a0base + 2 * A_STG * 2;
#pragma unroll
        for (int kh = 0; kh < 4; ++kh) {
            const int kc = kh * 16;
            unsigned a0[2][4], bA[4], bB[4];
            ldsm4(bA, bbase + (uint32_t)((b_gsel * 32 + b_jrow) * PITCH + kc + b_kadd) * 2);
            ldsm4(bB, bbase + (uint32_t)(((2 + b_gsel) * 32 + b_jrow) * PITCH + kc + b_kadd) * 2);
#pragma unroll
            for (int mi = 0; mi < 2; ++mi) {
                const int row = wm * 32 + mi * 16 + arow_off;
                ldsm4(a0[mi], a0base + (uint32_t)(row * PITCH + kc + acol_off) * 2);
            }
#pragma unroll
            for (int mi = 0; mi < 2; ++mi) {
                mma_bf16(acc[mi][0], a0[mi], bA[0], bA[2]);
                mma_bf16(acc[mi][1], a0[mi], bA[1], bA[3]);
                mma_bf16(acc[mi][2], a0[mi], bB[0], bB[2]);
                mma_bf16(acc[mi][3], a0[mi], bB[1], bB[3]);
            }
            if (phA) {
                unsigned a1[2][4];
#pragma unroll
                for (int mi = 0; mi < 2; ++mi) {
                    const int row = wm * 32 + mi * 16 + arow_off;
                    ldsm4(a1[mi], a1base + (uint32_t)(row * PITCH + kc + acol_off) * 2);
                }
#pragma unroll
                for (int mi = 0; mi < 2; ++mi) {
                    mma_bf16(acc[mi][0], a1[mi], bA[0], bA[2]);
                    mma_bf16(acc[mi][1], a1[mi], bA[1], bA[3]);
                    mma_bf16(acc[mi][2], a1[mi], bB[0], bB[2]);
                    mma_bf16(acc[mi][3], a1[mi], bB[1], bB[3]);
                }
            }
        }
    };

    load_stage(0, 0);
    load_stage(1, 1);

    for (int ci = 0; ci < NCH2; ++ci) {
        if (ci + 1 < NCH2) { CP_WAIT(1); } else { CP_WAIT(0); }
        __syncthreads();
        if (ci + 2 < NCH2) load_stage(ci + 2, (ci + 2) % 3);
        compute(ci, ci % 3);
    }

    // ---------------- in-register epilogue ----------------
    const int g4 = lane >> 2, tg = lane & 3;
    const int j = j0 + wn * 8 + tg * 2;

    float2 bsum[4];
#pragma unroll
    for (int g = 0; g < 4; ++g) {
        const float2 bi = *reinterpret_cast<const float2*>(bih + g * HH + j);
        const float2 bh = *reinterpret_cast<const float2*>(bhh + g * HH + j);
        bsum[g] = make_float2(bi.x + bh.x, bi.y + bh.y);
    }
#pragma unroll
    for (int mi = 0; mi < 2; ++mi)
#pragma unroll
        for (int rh = 0; rh < 2; ++rh) {
            const int b = b0 + wm * 32 + mi * 16 + g4 + rh * 8;
            float2 gv[4];
#pragma unroll
            for (int g = 0; g < 4; ++g)
                gv[g] = make_float2(acc[mi][g][rh * 2] + bsum[g].x,
                                    acc[mi][g][rh * 2 + 1] + bsum[g].y);
            const size_t off = (size_t)b * HH + j;
            // c may have been written by a different CTA (previous step) -> L2 read
            const float2 cv = __ldcg(reinterpret_cast<const float2*>(c + off));

            const float i0 = sigm(gv[0].x), i1 = sigm(gv[0].y);
            const float f0 = sigm(gv[1].x), f1 = sigm(gv[1].y);
            const float g0 = tanhf(gv[2].x), g1 = tanhf(gv[2].y);
            const float o0 = sigm(gv[3].x), o1 = sigm(gv[3].y);
            const float cn0 = f0 * cv.x + i0 * g0;
            const float cn1 = f1 * cv.y + i1 * g1;
            *reinterpret_cast<float2*>(c + off) = make_float2(cn0, cn1);
            const float hn0 = o0 * tanhf(cn0);
            const float hn1 = o1 * tanhf(cn1);
            const bf16 h0 = __float2bfloat16(hn0);
            const bf16 h1 = __float2bfloat16(hn1);
            __nv_bfloat162 hi2 = __nv_bfloat162(h0, h1);
            __nv_bfloat162 lo2 = __nv_bfloat162(
                __float2bfloat16(hn0 - __bfloat162float(h0)),
                __float2bfloat16(hn1 - __bfloat162float(h1)));
            *reinterpret_cast<__nv_bfloat162*>(ho_hi + off) = hi2;
            *reinterpret_cast<__nv_bfloat162*>(ho_lo + off) = lo2;
        }
}

// ---------------------------------------------------------------------------
// Persistent scheduler kernel: global cursor over (t, role-tile) jobs.
// Monotone cursor + flag waits => deadlock-free at ANY residency.
// ---------------------------------------------------------------------------
__global__ __launch_bounds__(256, 2)
void persistent_kernel(const float* __restrict__ bih1, const float* __restrict__ bhh1,
                       const float* __restrict__ bih2, const float* __restrict__ bhh2,
                       const float* __restrict__ bih3, const float* __restrict__ bhh3)
{
    extern __shared__ __align__(16) bf16 dyn[];
    __shared__ int job_sh;
    const int tid = threadIdx.x;

    for (;;) {
        if (tid == 0) job_sh = atomicAdd(&g_cursor, 1);
        __syncthreads();
        const int job = job_sh;
        if (job >= TOTAL_JOBS) break;
        const int t = job / JOBS_PER_T;
        const int r = job - t * JOBS_PER_T;
        const int pi = t & 1, po = (t + 1) & 1;

        if (r < 128) {
            // L1: reads x_t, h1[pi]; writes h1[po], c1
            if (t >= 1) flag_wait(&g_f1[t - 1], 128);   // RAW h1[pi] (+c1)
            if (t >= 2) flag_wait(&g_f2[t - 2], 128);   // WAR h1[po] vs L2(t-2)
            lstm_tile<DIN, H1, H1>(
                g_x_hi + (size_t)t * BB * DIN, g_x_lo + (size_t)t * BB * DIN,
                g_h1_hi[pi], g_h1_lo[pi],
                g_W1i_hi, g_W1i_lo, g_W1h_hi, g_W1h_lo,
                bih1, bhh1, g_c1, g_h1_hi[po], g_h1_lo[po],
                (r & 31) * 32, (r >> 5) * 64, dyn);
            flag_arrive(&g_f1[t]);
        } else if (r < 256) {
            const int q = r - 128;
            // L2: reads h1[po], h2[pi]; writes h2[po], c2
            flag_wait(&g_f1[t], 128);                    // RAW h1[po]
            if (t >= 1) flag_wait(&g_f2[t - 1], 128);    // RAW h2[pi] (+c2)
            if (t >= 2) flag_wait(&g_f3[t - 2], 64);     // WAR h2[po] vs L3(t-2)
            lstm_tile<H1, H2, H2>(
                g_h1_hi[po], g_h1_lo[po], g_h2_hi[pi], g_h2_lo[pi],
                g_W2i_hi, g_W2i_lo, g_W2h_hi, g_W2h_lo,
                bih2, bhh2, g_c2, g_h2_hi[po], g_h2_lo[po],
                (q & 31) * 32, (q >> 5) * 64, dyn);
            flag_arrive(&g_f2[t]);
        } else {
            const int q = r - 256;
            // L3: reads h2[po], h3[pi]; writes h3[po], c3
            flag_wait(&g_f2[t], 128);                    // RAW h2[po]
            if (t >= 1) flag_wait(&g_f3[t - 1], 64);     // RAW h3[pi] (+c3, WAR h3[po])
            lstm_tile<H2, H3, H3>(
                g_h2_hi[po], g_h2_lo[po], g_h3_hi[pi], g_h3_lo[pi],
                g_W3i_hi, g_W3i_lo, g_W3h_hi, g_W3h_lo,
                bih3, bhh3, g_c3, g_h3_hi[po], g_h3_lo[po],
                (q & 15) * 32, (q >> 4) * 64, dyn);
            flag_arrive(&g_f3[t]);
        }
    }
}

// ---------------- prep / init / finalize ------------------------------------
__global__ void split_kernel(const float* __restrict__ src, bf16* __restrict__ hi,
                             bf16* __restrict__ lo, int n) {
    int i = blockIdx.x * blockDim.x + threadIdx.x;
    const int st = gridDim.x * blockDim.x;
    for (; i < n; i += st) {
        const float v = src[i];
        const bf16 h = __float2bfloat16(v);
        hi[i] = h;
        lo[i] = __float2bfloat16(v - __bfloat162float(h));
    }
}

__global__ void init_state_kernel() {
    int idx = blockIdx.x * blockDim.x + threadIdx.x;
    const int st = gridDim.x * blockDim.x;
    const int N1 = BB * H1, N3 = BB * H3;
    const bf16 z = __float2bfloat16(0.0f);
    for (int i = idx; i < N1; i += st) {
        g_h1_hi[0][i] = z; g_h1_lo[0][i] = z; g_h1_hi[1][i] = z; g_h1_lo[1][i] = z;
        g_h2_hi[0][i] = z; g_h2_lo[0][i] = z; g_h2_hi[1][i] = z; g_h2_lo[1][i] = z;
        g_c1[i] = 0.f; g_c2[i] = 0.f;
    }
    for (int i = idx; i < N3; i += st) {
        g_h3_hi[0][i] = z; g_h3_lo[0][i] = z; g_h3_hi[1][i] = z; g_h3_lo[1][i] = z;
        g_c3[i] = 0.f;
    }
    for (int i = idx; i < TT; i += st) {
        g_f1[i] = 0; g_f2[i] = 0; g_f3[i] = 0;
    }
    if (idx == 0) g_cursor = 0;
}

__global__ void finalize_kernel(float* __restrict__ out) {
    int idx = blockIdx.x * blockDim.x + threadIdx.x;
    const int st = gridDim.x * blockDim.x;
    const int N1 = BB * H1, N3 = BB * H3;
    for (int i = idx; i < N1; i += st) {
        out[0 * N1 + i] = __bfloat162float(g_h1_hi[0][i]) + __bfloat162float(g_h1_lo[0][i]);
        out[1 * N1 + i] = g_c1[i];
        out[2 * N1 + i] = __bfloat162float(g_h2_hi[0][i]) + __bfloat162float(g_h2_lo[0][i]);
        out[3 * N1 + i] = g_c2[i];
    }
    for (int i = idx; i < N3; i += st) {
        out[4 * N1 + i] = __bfloat162float(g_h3_hi[0][i]) + __bfloat162float(g_h3_lo[0][i]);
        out[4 * N1 + N3 + i] = g_c3[i];
    }
}

// ---------------- launch ----------------------------------------------------
extern "C" void kernel_launch(void* const* d_in, const int* in_sizes, int n_in,
                              void* d_out, int out_size) {
    const float* x    = (const float*)d_in[0];
    const float* Wih1 = (const float*)d_in[1];
    const float* Whh1 = (const float*)d_in[2];
    const float* bih1 = (const float*)d_in[3];
    const float* bhh1 = (const float*)d_in[4];
    const float* Wih2 = (const float*)d_in[5];
    const float* Whh2 = (const float*)d_in[6];
    const float* bih2 = (const float*)d_in[7];
    const float* bhh2 = (const float*)d_in[8];
    const float* Wih3 = (const float*)d_in[9];
    const float* Whh3 = (const float*)d_in[10];
    const float* bih3 = (const float*)d_in[11];
    const float* bhh3 = (const float*)d_in[12];
    float* out = (float*)d_out;

    bf16 *x_hi, *x_lo;
    bf16 *W1i_hi, *W1i_lo, *W1h_hi, *W1h_lo;
    bf16 *W2i_hi, *W2i_lo, *W2h_hi, *W2h_lo;
    bf16 *W3i_hi, *W3i_lo, *W3h_hi, *W3h_lo;

    cudaGetSymbolAddress((void**)&x_hi, g_x_hi);
    cudaGetSymbolAddress((void**)&x_lo, g_x_lo);
    cudaGetSymbolAddress((void**)&W1i_hi, g_W1i_hi);
    cudaGetSymbolAddress((void**)&W1i_lo, g_W1i_lo);
    cudaGetSymbolAddress((void**)&W1h_hi, g_W1h_hi);
    cudaGetSymbolAddress((void**)&W1h_lo, g_W1h_lo);
    cudaGetSymbolAddress((void**)&W2i_hi, g_W2i_hi);
    cudaGetSymbolAddress((void**)&W2i_lo, g_W2i_lo);
    cudaGetSymbolAddress((void**)&W2h_hi, g_W2h_hi);
    cudaGetSymbolAddress((void**)&W2h_lo, g_W2h_lo);
    cudaGetSymbolAddress((void**)&W3i_hi, g_W3i_hi);
    cudaGetSymbolAddress((void**)&W3i_lo, g_W3i_lo);
    cudaGetSymbolAddress((void**)&W3h_hi, g_W3h_hi);
    cudaGetSymbolAddress((void**)&W3h_lo, g_W3h_lo);

    cudaFuncSetAttribute(persistent_kernel,
                         cudaFuncAttributeMaxDynamicSharedMemorySize, DYN_BYTES);

    // prologue: splits + state/flag init (all default stream)
    split_kernel<<<2048, 256>>>(x, x_hi, x_lo, TT * BB * DIN);
    split_kernel<<<1024, 256>>>(Wih1, W1i_hi, W1i_lo, 4 * H1 * DIN);
    split_kernel<<<1024, 256>>>(Whh1, W1h_hi, W1h_lo, 4 * H1 * H1);
    split_kernel<<<1024, 256>>>(Wih2, W2i_hi, W2i_lo, 4 * H2 * H1);
    split_kernel<<<1024, 256>>>(Whh2, W2h_hi, W2h_lo, 4 * H2 * H2);
    split_kernel<<<1024, 256>>>(Wih3, W3i_hi, W3i_lo, 4 * H3 * H2);
    split_kernel<<<1024, 256>>>(Whh3, W3h_hi, W3h_lo, 4 * H3 * H3);
    init_state_kernel<<<512, 256>>>();

    // one persistent kernel runs the whole recurrence
    persistent_kernel<<<288, 256, DYN_BYTES>>>(bih1, bhh1, bih2, bhh2, bih3, bhh3);

    finalize_kernel<<<256, 256>>>(out);
}

// round 12
// speedup vs baseline: 1.0670x; 1.0670x over previous
#include <cuda_runtime.h>
#include <cuda_bf16.h>
#include <math.h>
#include <cstdint>

#define TT 128
#define BB 256
#define DIN 512
#define H1 1024
#define H2 1024
#define H3 512

typedef __nv_bfloat16 bf16;

// ---------------- persistent device storage ---------------------------------
__device__ bf16 g_x_hi[TT * BB * DIN];
__device__ bf16 g_x_lo[TT * BB * DIN];

__device__ bf16 g_W1i_hi[4 * H1 * DIN], g_W1i_lo[4 * H1 * DIN];
__device__ bf16 g_W1h_hi[4 * H1 * H1],  g_W1h_lo[4 * H1 * H1];
__device__ bf16 g_W2i_hi[4 * H2 * H1],  g_W2i_lo[4 * H2 * H1];
__device__ bf16 g_W2h_hi[4 * H2 * H2],  g_W2h_lo[4 * H2 * H2];
__device__ bf16 g_W3i_hi[4 * H3 * H2],  g_W3i_lo[4 * H3 * H2];
__device__ bf16 g_W3h_hi[4 * H3 * H3],  g_W3h_lo[4 * H3 * H3];

__device__ bf16 g_h1_hi[2][BB * H1], g_h1_lo[2][BB * H1];
__device__ bf16 g_h2_hi[2][BB * H2], g_h2_lo[2][BB * H2];
__device__ bf16 g_h3_hi[2][BB * H3], g_h3_lo[2][BB * H3];

__device__ float g_c1[BB * H1], g_c2[BB * H2], g_c3[BB * H3];

// scheduler state
__device__ int g_cursor;
__device__ int g_f1[TT], g_f2[TT], g_f3[TT];

#define TOTAL_JOBS (TT * 320)     // 128*(128 L1 + 128 L2 + 64 L3)

// ---------------- helpers ----------------------------------------------------
__device__ __forceinline__ uint32_t smem_u32(const void* p) {
    uint32_t a;
    asm("{ .reg .u64 t; cvta.to.shared.u64 t, %1; cvt.u32.u64 %0, t; }" : "=r"(a) : "l"(p));
    return a;
}
__device__ __forceinline__ void cp16(uint32_t smem, const void* gmem) {
    asm volatile("cp.async.cg.shared.global [%0], [%1], 16;\n" ::"r"(smem), "l"(gmem));
}
#define CP_COMMIT() asm volatile("cp.async.commit_group;\n" ::: "memory")
#define CP_WAIT(n)  asm volatile("cp.async.wait_group %0;\n" ::"n"(n) : "memory")

__device__ __forceinline__ void ldsm4(unsigned* d, uint32_t addr) {
    asm volatile("ldmatrix.sync.aligned.m8n8.x4.shared.b16 {%0,%1,%2,%3}, [%4];"
                 : "=r"(d[0]), "=r"(d[1]), "=r"(d[2]), "=r"(d[3]) : "r"(addr));
}
__device__ __forceinline__ void mma_bf16(float* c, const unsigned* a, unsigned b0, unsigned b1) {
    asm volatile(
        "mma.sync.aligned.m16n8k16.row.col.f32.bf16.bf16.f32 "
        "{%0,%1,%2,%3},{%4,%5,%6,%7},{%8,%9},{%0,%1,%2,%3};\n"
        : "+f"(c[0]), "+f"(c[1]), "+f"(c[2]), "+f"(c[3])
        : "r"(a[0]), "r"(a[1]), "r"(a[2]), "r"(a[3]), "r"(b0), "r"(b1));
}
__device__ __forceinline__ float sigm(float x) { return 1.0f / (1.0f + __expf(-x)); }

__device__ __forceinline__ void flag_arrive(int* f) {
    __threadfence();
    __syncthreads();
    if (threadIdx.x == 0) atomicAdd(f, 1);
}
__device__ __forceinline__ void flag_wait(int* f, int target) {
    if (threadIdx.x == 0) {
        volatile int* vf = (volatile int*)f;
        while (*vf < target) __nanosleep(64);
    }
    __syncthreads();
    __threadfence();
}

// ---------------------------------------------------------------------------
// One LSTM tile (identical to the R10 passing version).
// ---------------------------------------------------------------------------
#define BM 64
#define PITCH 72
#define A_STG (BM * PITCH)
#define B_STG (128 * PITCH)
#define STG_ELEMS (2 * A_STG + B_STG)
#define DYN_BYTES (3 * STG_ELEMS * 2)   // 110592 bytes

template <int K1, int K2, int HH>
__device__ void lstm_tile(const bf16* __restrict__ Ai_hi, const bf16* __restrict__ Ai_lo,
                          const bf16* __restrict__ Ah_hi, const bf16* __restrict__ Ah_lo,
                          const bf16* __restrict__ Wi_hi, const bf16* __restrict__ Wi_lo,
                          const bf16* __restrict__ Wh_hi, const bf16* __restrict__ Wh_lo,
                          const float* __restrict__ bih, const float* __restrict__ bhh,
                          float* __restrict__ c,
                          bf16* __restrict__ ho_hi, bf16* __restrict__ ho_lo,
                          int j0, int b0, bf16* dyn)
{
    constexpr int KK = K1 + K2;
    constexpr int KKc = KK / 64;
    constexpr int NCH2 = 2 * KKc;

    const uint32_t sbase = smem_u32(dyn);
    const int tid = threadIdx.x;
    const int wid = tid >> 5, lane = tid & 31;
    const int wm = wid >> 2, wn = wid & 3;

    float acc[2][4][4];
#pragma unroll
    for (int mi = 0; mi < 2; ++mi)
#pragma unroll
        for (int g = 0; g < 4; ++g)
#pragma unroll
            for (int r = 0; r < 4; ++r) acc[mi][g][r] = 0.0f;

    auto load_stage = [&](int ci, int s) {
        const bool phA = ci < KKc;
        const int kk = (phA ? ci : ci - KKc) * 64;
        const bf16 *Ah, *Al, *W;
        int col, ld;
        if (kk < K1) {
            Ah = Ai_hi; Al = Ai_lo;
            W = phA ? Wi_hi : Wi_lo;
            col = kk; ld = K1;
        } else {
            Ah = Ah_hi; Al = Ah_lo;
            W = phA ? Wh_hi : Wh_lo;
            col = kk - K1; ld = K2;
        }
        const uint32_t a0base = sbase + (uint32_t)(s * STG_ELEMS) * 2;
        const uint32_t a1base = a0base + A_STG * 2;
        const uint32_t bbase  = a0base + 2 * A_STG * 2;
#pragma unroll
        for (int it = 0; it < 2; ++it) {
            const int idx = tid + it * 256;
            const int r = idx >> 3, q = idx & 7;
            cp16(a0base + (uint32_t)(r * PITCH + q * 8) * 2,
                 Ah + (size_t)(b0 + r) * ld + col + q * 8);
        }
        if (phA) {
#pragma unroll
            for (int it = 0; it < 2; ++it) {
                const int idx = tid + it * 256;
                const int r = idx >> 3, q = idx & 7;
                cp16(a1base + (uint32_t)(r * PITCH + q * 8) * 2,
                     Al + (size_t)(b0 + r) * ld + col + q * 8);
            }
        }
#pragma unroll
        for (int it = 0; it < 4; ++it) {
            const int idx = tid + it * 256;
            const int r = idx >> 3, q = idx & 7;
            const int gate = r >> 5, jl = r & 31;
            cp16(bbase + (uint32_t)(r * PITCH + q * 8) * 2,
                 W + (size_t)(gate * HH + j0 + jl) * ld + col + q * 8);
        }
        CP_COMMIT();
    };

    const int arow_off = lane & 15, acol_off = (lane >> 4) << 3;
    const int b_gsel = (lane >> 3) & 1;
    const int b_kadd = (lane >> 4) << 3;
    const int b_jrow = wn * 8 + (lane & 7);

    auto compute = [&](int ci, int s) {
        const bool phA = ci < KKc;
        const uint32_t a0base = sbase + (uint32_t)(s * STG_ELEMS) * 2;
        const uint32_t a1base = a0base + A_STG * 2;
        const uint32_t bbase  = a0base + 2 * A_STG * 2;
#pragma unroll
        for (int kh = 0; kh < 4; ++kh) {
            const int kc = kh * 16;
            unsigned a0[2][4], bA[4], bB[4];
            ldsm4(bA, bbase + (uint32_t)((b_gsel * 32 + b_jrow) * PITCH + kc + b_kadd) * 2);
            ldsm4(bB, bbase + (uint32_t)(((2 + b_gsel) * 32 + b_jrow) * PITCH + kc + b_kadd) * 2);
#pragma unroll
            for (int mi = 0; mi < 2; ++mi) {
                const int row = wm * 32 + mi * 16 + arow_off;
                ldsm4(a0[mi], a0base + (uint32_t)(row * PITCH + kc + acol_off) * 2);
            }
#pragma unroll
            for (int mi = 0; mi < 2; ++mi) {
                mma_bf16(acc[mi][0], a0[mi], bA[0], bA[2]);
                mma_bf16(acc[mi][1], a0[mi], bA[1], bA[3]);
                mma_bf16(acc[mi][2], a0[mi], bB[0], bB[2]);
                mma_bf16(acc[mi][3], a0[mi], bB[1], bB[3]);
            }
            if (phA) {
                unsigned a1[2][4];
#pragma unroll
                for (int mi = 0; mi < 2; ++mi) {
                    const int row = wm * 32 + mi * 16 + arow_off;
                    ldsm4(a1[mi], a1base + (uint32_t)(row * PITCH + kc + acol_off) * 2);
                }
#pragma unroll
                for (int mi = 0; mi < 2; ++mi) {
                    mma_bf16(acc[mi][0], a1[mi], bA[0], bA[2]);
                    mma_bf16(acc[mi][1], a1[mi], bA[1], bA[3]);
                    mma_bf16(acc[mi][2], a1[mi], bB[0], bB[2]);
                    mma_bf16(acc[mi][3], a1[mi], bB[1], bB[3]);
                }
            }
        }
    };

    load_stage(0, 0);
    load_stage(1, 1);

    for (int ci = 0; ci < NCH2; ++ci) {
        if (ci + 1 < NCH2) { CP_WAIT(1); } else { CP_WAIT(0); }
        __syncthreads();
        if (ci + 2 < NCH2) load_stage(ci + 2, (ci + 2) % 3);
        compute(ci, ci % 3);
    }

    const int g4 = lane >> 2, tg = lane & 3;
    const int j = j0 + wn * 8 + tg * 2;

    float2 bsum[4];
#pragma unroll
    for (int g = 0; g < 4; ++g) {
        const float2 bi = *reinterpret_cast<const float2*>(bih + g * HH + j);
        const float2 bh = *reinterpret_cast<const float2*>(bhh + g * HH + j);
        bsum[g] = make_float2(bi.x + bh.x, bi.y + bh.y);
    }
#pragma unroll
    for (int mi = 0; mi < 2; ++mi)
#pragma unroll
        for (int rh = 0; rh < 2; ++rh) {
            const int b = b0 + wm * 32 + mi * 16 + g4 + rh * 8;
            float2 gv[4];
#pragma unroll
            for (int g = 0; g < 4; ++g)
                gv[g] = make_float2(acc[mi][g][rh * 2] + bsum[g].x,
                                    acc[mi][g][rh * 2 + 1] + bsum[g].y);
            const size_t off = (size_t)b * HH + j;
            const float2 cv = __ldcg(reinterpret_cast<const float2*>(c + off));

            const float i0 = sigm(gv[0].x), i1 = sigm(gv[0].y);
            const float f0 = sigm(gv[1].x), f1 = sigm(gv[1].y);
            const float g0 = tanhf(gv[2].x), g1 = tanhf(gv[2].y);
            const float o0 = sigm(gv[3].x), o1 = sigm(gv[3].y);
            const float cn0 = f0 * cv.x + i0 * g0;
            const float cn1 = f1 * cv.y + i1 * g1;
            *reinterpret_cast<float2*>(c + off) = make_float2(cn0, cn1);
            const float hn0 = o0 * tanhf(cn0);
            const float hn1 = o1 * tanhf(cn1);
            const bf16 h0 = __float2bfloat16(hn0);
            const bf16 h1 = __float2bfloat16(hn1);
            __nv_bfloat162 hi2 = __nv_bfloat162(h0, h1);
            __nv_bfloat162 lo2 = __nv_bfloat162(
                __float2bfloat16(hn0 - __bfloat162float(h0)),
                __float2bfloat16(hn1 - __bfloat162float(h1)));
            *reinterpret_cast<__nv_bfloat162*>(ho_hi + off) = hi2;
            *reinterpret_cast<__nv_bfloat162*>(ho_lo + off) = lo2;
        }
}

// ---------------------------------------------------------------------------
// Persistent scheduler with SOFTWARE-PIPELINED job order.
// Stage p = { L1(t=p) [128], L2(t=p-1) [128], L3(t=p-2) [64] }: all jobs in
// a stage are mutually independent and depend only on stages <= p-1.
// Flat job layout:
//   stage 0:            128 jobs   (L1 t=0)                      [0, 128)
//   stage 1:            256 jobs   (L1 t=1, L2 t=0)              [128, 384)
//   stages 2..127:      320 each   (L1 p, L2 p-1, L3 p-2)        [384, 40704)
//   stage 128:          192 jobs   (L2 127, L3 126)              [40704, 40896)
//   stage 129:           64 jobs   (L3 127)                      [40896, 40960)
// ---------------------------------------------------------------------------
__global__ __launch_bounds__(256, 2)
void persistent_kernel(const float* __restrict__ bih1, const float* __restrict__ bhh1,
                       const float* __restrict__ bih2, const float* __restrict__ bhh2,
                       const float* __restrict__ bih3, const float* __restrict__ bhh3)
{
    extern __shared__ __align__(16) bf16 dyn[];
    __shared__ int job_sh;
    const int tid = threadIdx.x;

    for (;;) {
        if (tid == 0) job_sh = atomicAdd(&g_cursor, 1);
        __syncthreads();
        const int job = job_sh;
        if (job >= TOTAL_JOBS) break;

        int role, t, tile;   // role: 0=L1, 1=L2, 2=L3
        if (job < 128) {
            role = 0; t = 0; tile = job;
        } else if (job < 384) {
            const int r = job - 128;
            if (r < 128) { role = 0; t = 1; tile = r; }
            else         { role = 1; t = 0; tile = r - 128; }
        } else if (job < 40704) {
            const int p = 2 + (job - 384) / 320;
            const int r = (job - 384) % 320;
            if (r < 128)      { role = 0; t = p;     tile = r; }
            else if (r < 256) { role = 1; t = p - 1; tile = r - 128; }
            else              { role = 2; t = p - 2; tile = r - 256; }
        } else if (job < 40896) {
            const int r = job - 40704;
            if (r < 128) { role = 1; t = 127; tile = r; }
            else         { role = 2; t = 126; tile = r - 128; }
        } else {
            role = 2; t = 127; tile = job - 40896;
        }

        const int pi = t & 1, po = (t + 1) & 1;

        if (role == 0) {
            // L1: reads x_t, h1[pi]; writes h1[po], c1
            if (t >= 1) flag_wait(&g_f1[t - 1], 128);   // RAW h1[pi] (+c1)
            if (t >= 2) flag_wait(&g_f2[t - 2], 128);   // WAR h1[po] vs L2(t-2)
            lstm_tile<DIN, H1, H1>(
                g_x_hi + (size_t)t * BB * DIN, g_x_lo + (size_t)t * BB * DIN,
                g_h1_hi[pi], g_h1_lo[pi],
                g_W1i_hi, g_W1i_lo, g_W1h_hi, g_W1h_lo,
                bih1, bhh1, g_c1, g_h1_hi[po], g_h1_lo[po],
                (tile & 31) * 32, (tile >> 5) * 64, dyn);
            flag_arrive(&g_f1[t]);
        } else if (role == 1) {
            // L2: reads h1[po], h2[pi]; writes h2[po], c2
            flag_wait(&g_f1[t], 128);                    // RAW h1[po]
            if (t >= 1) flag_wait(&g_f2[t - 1], 128);    // RAW h2[pi] (+c2)
            if (t >= 2) flag_wait(&g_f3[t - 2], 64);     // WAR h2[po] vs L3(t-2)
            lstm_tile<H1, H2, H2>(
                g_h1_hi[po], g_h1_lo[po], g_h2_hi[pi], g_h2_lo[pi],
                g_W2i_hi, g_W2i_lo, g_W2h_hi, g_W2h_lo,
                bih2, bhh2, g_c2, g_h2_hi[po], g_h2_lo[po],
                (tile & 31) * 32, (tile >> 5) * 64, dyn);
            flag_arrive(&g_f2[t]);
        } else {
            // L3: reads h2[po], h3[pi]; writes h3[po], c3
            flag_wait(&g_f2[t], 128);                    // RAW h2[po]
            if (t >= 1) flag_wait(&g_f3[t - 1], 64);     // RAW h3[pi] (+c3, WAR h3[po])
            lstm_tile<H2, H3, H3>(
                g_h2_hi[po], g_h2_lo[po], g_h3_hi[pi], g_h3_lo[pi],
                g_W3i_hi, g_W3i_lo, g_W3h_hi, g_W3h_lo,
                bih3, bhh3, g_c3, g_h3_hi[po], g_h3_lo[po],
                (tile & 15) * 32, (tile >> 4) * 64, dyn);
            flag_arrive(&g_f3[t]);
        }
    }
}

// ---------------- prep / init / finalize ------------------------------------
__global__ void split_kernel(const float* __restrict__ src, bf16* __restrict__ hi,
                             bf16* __restrict__ lo, int n) {
    int i = blockIdx.x * blockDim.x + threadIdx.x;
    const int st = gridDim.x * blockDim.x;
    for (; i < n; i += st) {
        const float v = src[i];
        const bf16 h = __float2bfloat16(v);
        hi[i] = h;
        lo[i] = __float2bfloat16(v - __bfloat162float(h));
    }
}

__global__ void init_state_kernel() {
    int idx = blockIdx.x * blockDim.x + threadIdx.x;
    const int st = gridDim.x * blockDim.x;
    const int N1 = BB * H1, N3 = BB * H3;
    const bf16 z = __float2bfloat16(0.0f);
    for (int i = idx; i < N1; i += st) {
        g_h1_hi[0][i] = z; g_h1_lo[0][i] = z; g_h1_hi[1][i] = z; g_h1_lo[1][i] = z;
        g_h2_hi[0][i] = z; g_h2_lo[0][i] = z; g_h2_hi[1][i] = z; g_h2_lo[1][i] = z;
        g_c1[i] = 0.f; g_c2[i] = 0.f;
    }
    for (int i = idx; i < N3; i += st) {
        g_h3_hi[0][i] = z; g_h3_lo[0][i] = z; g_h3_hi[1][i] = z; g_h3_lo[1][i] = z;
        g_c3[i] = 0.f;
    }
    for (int i = idx; i < TT; i += st) {
        g_f1[i] = 0; g_f2[i] = 0; g_f3[i] = 0;
    }
    if (idx == 0) g_cursor = 0;
}

__global__ void finalize_kernel(float* __restrict__ out) {
    int idx = blockIdx.x * blockDim.x + threadIdx.x;
    const int st = gridDim.x * blockDim.x;
    const int N1 = BB * H1, N3 = BB * H3;
    for (int i = idx; i < N1; i += st) {
        out[0 * N1 + i] = __bfloat162float(g_h1_hi[0][i]) + __bfloat162float(g_h1_lo[0][i]);
        out[1 * N1 + i] = g_c1[i];
        out[2 * N1 + i] = __bfloat162float(g_h2_hi[0][i]) + __bfloat162float(g_h2_lo[0][i]);
        out[3 * N1 + i] = g_c2[i];
    }
    for (int i = idx; i < N3; i += st) {
        out[4 * N1 + i] = __bfloat162float(g_h3_hi[0][i]) + __bfloat162float(g_h3_lo[0][i]);
        out[4 * N1 + N3 + i] = g_c3[i];
    }
}

// ---------------- launch ----------------------------------------------------
extern "C" void kernel_launch(void* const* d_in, const int* in_sizes, int n_in,
                              void* d_out, int out_size) {
    const float* x    = (const float*)d_in[0];
    const float* Wih1 = (const float*)d_in[1];
    const float* Whh1 = (const float*)d_in[2];
    const float* bih1 = (const float*)d_in[3];
    const float* bhh1 = (const float*)d_in[4];
    const float* Wih2 = (const float*)d_in[5];
    const float* Whh2 = (const float*)d_in[6];
    const float* bih2 = (const float*)d_in[7];
    const float* bhh2 = (const float*)d_in[8];
    const float* Wih3 = (const float*)d_in[9];
    const float* Whh3 = (const float*)d_in[10];
    const float* bih3 = (const float*)d_in[11];
    const float* bhh3 = (const float*)d_in[12];
    float* out = (float*)d_out;

    bf16 *x_hi, *x_lo;
    bf16 *W1i_hi, *W1i_lo, *W1h_hi, *W1h_lo;
    bf16 *W2i_hi, *W2i_lo, *W2h_hi, *W2h_lo;
    bf16 *W3i_hi, *W3i_lo, *W3h_hi, *W3h_lo;

    cudaGetSymbolAddress((void**)&x_hi, g_x_hi);
    cudaGetSymbolAddress((void**)&x_lo, g_x_lo);
    cudaGetSymbolAddress((void**)&W1i_hi, g_W1i_hi);
    cudaGetSymbolAddress((void**)&W1i_lo, g_W1i_lo);
    cudaGetSymbolAddress((void**)&W1h_hi, g_W1h_hi);
    cudaGetSymbolAddress((void**)&W1h_lo, g_W1h_lo);
    cudaGetSymbolAddress((void**)&W2i_hi, g_W2i_hi);
    cudaGetSymbolAddress((void**)&W2i_lo, g_W2i_lo);
    cudaGetSymbolAddress((void**)&W2h_hi, g_W2h_hi);
    cudaGetSymbolAddress((void**)&W2h_lo, g_W2h_lo);
    cudaGetSymbolAddress((void**)&W3i_hi, g_W3i_hi);
    cudaGetSymbolAddress((void**)&W3i_lo, g_W3i_lo);
    cudaGetSymbolAddress((void**)&W3h_hi, g_W3h_hi);
    cudaGetSymbolAddress((void**)&W3h_lo, g_W3h_lo);

    cudaFuncSetAttribute(persistent_kernel,
                         cudaFuncAttributeMaxDynamicSharedMemorySize, DYN_BYTES);

    split_kernel<<<2048, 256>>>(x, x_hi, x_lo, TT * BB * DIN);
    split_kernel<<<1024, 256>>>(Wih1, W1i_hi, W1i_lo, 4 * H1 * DIN);
    split_kernel<<<1024, 256>>>(Whh1, W1h_hi, W1h_lo, 4 * H1 * H1);
    split_kernel<<<1024, 256>>>(Wih2, W2i_hi, W2i_lo, 4 * H2 * H1);
    split_kernel<<<1024, 256>>>(Whh2, W2h_hi, W2h_lo, 4 * H2 * H2);
    split_kernel<<<1024, 256>>>(Wih3, W3i_hi, W3i_lo, 4 * H3 * H2);
    split_kernel<<<1024, 256>>>(Whh3, W3h_hi, W3h_lo, 4 * H3 * H3);
    init_state_kernel<<<512, 256>>>();

    persistent_kernel<<<296, 256, DYN_BYTES>>>(bih1, bhh1, bih2, bhh2, bih3, bhh3);

    finalize_kernel<<<256, 256>>>(out);
}

// round 13
// speedup vs baseline: 1.2507x; 1.1722x over previous
#include <cuda_runtime.h>
#include <cuda_bf16.h>
#include <cuda_fp8.h>
#include <math.h>
#include <cstdint>

#define TT 128
#define BB 256
#define DIN 512
#define H1 1024
#define H2 1024
#define H3 512

typedef __nv_bfloat16 bf16;
typedef __nv_fp8_e4m3 fp8;

// Scales: cross1 = (x_lo*256)*(w*4) = 1024*x_lo*w ; cross2 = (x/4)*(w_lo*4096)
// = 1024*x*w_lo. Accumulate both in one fp8 pass, then acc *= 1/1024.
#define INV_S (1.0f / 1024.0f)

// ---------------- persistent device storage ---------------------------------
__device__ bf16 g_x_hi[TT * BB * DIN];
__device__ fp8  g_x_8h[TT * BB * DIN];     // e4m3(x/4)
__device__ fp8  g_x_8l[TT * BB * DIN];     // e4m3((x - x_hi)*256)
__device__ float g_xpre[(size_t)TT * BB * 4 * H1];

__device__ bf16 g_W1i_hi[4 * H1 * DIN]; __device__ fp8 g_W1i_8h[4 * H1 * DIN], g_W1i_8l[4 * H1 * DIN];
__device__ bf16 g_W1h_hi[4 * H1 * H1];  __device__ fp8 g_W1h_8h[4 * H1 * H1],  g_W1h_8l[4 * H1 * H1];
__device__ bf16 g_W2i_hi[4 * H2 * H1];  __device__ fp8 g_W2i_8h[4 * H2 * H1],  g_W2i_8l[4 * H2 * H1];
__device__ bf16 g_W2h_hi[4 * H2 * H2];  __device__ fp8 g_W2h_8h[4 * H2 * H2],  g_W2h_8l[4 * H2 * H2];
__device__ bf16 g_W3i_hi[4 * H3 * H2];  __device__ fp8 g_W3i_8h[4 * H3 * H2],  g_W3i_8l[4 * H3 * H2];
__device__ bf16 g_W3h_hi[4 * H3 * H3];  __device__ fp8 g_W3h_8h[4 * H3 * H3],  g_W3h_8l[4 * H3 * H3];

__device__ bf16 g_h1_hi[2][BB * H1]; __device__ fp8 g_h1_8h[2][BB * H1], g_h1_8l[2][BB * H1];
__device__ bf16 g_h2_hi[2][BB * H2]; __device__ fp8 g_h2_8h[2][BB * H2], g_h2_8l[2][BB * H2];
__device__ bf16 g_h3_hi[2][BB * H3]; __device__ fp8 g_h3_8h[2][BB * H3], g_h3_8l[2][BB * H3];

__device__ float g_c1[BB * H1], g_c2[BB * H2], g_c3[BB * H3];

// ---------------- helpers ----------------------------------------------------
__device__ __forceinline__ uint32_t smem_u32(const void* p) {
    uint32_t a;
    asm("{ .reg .u64 t; cvta.to.shared.u64 t, %1; cvt.u32.u64 %0, t; }" : "=r"(a) : "l"(p));
    return a;
}
__device__ __forceinline__ void cp16(uint32_t smem, const void* gmem) {
    asm volatile("cp.async.cg.shared.global [%0], [%1], 16;\n" ::"r"(smem), "l"(gmem));
}
#define CP_COMMIT() asm volatile("cp.async.commit_group;\n" ::: "memory")
#define CP_WAIT(n)  asm volatile("cp.async.wait_group %0;\n" ::"n"(n) : "memory")

__device__ __forceinline__ void ldsm4(unsigned* d, uint32_t addr) {
    asm volatile("ldmatrix.sync.aligned.m8n8.x4.shared.b16 {%0,%1,%2,%3}, [%4];"
                 : "=r"(d[0]), "=r"(d[1]), "=r"(d[2]), "=r"(d[3]) : "r"(addr));
}
__device__ __forceinline__ void mma_bf16(float* c, const unsigned* a, unsigned b0, unsigned b1) {
    asm volatile(
        "mma.sync.aligned.m16n8k16.row.col.f32.bf16.bf16.f32 "
        "{%0,%1,%2,%3},{%4,%5,%6,%7},{%8,%9},{%0,%1,%2,%3};\n"
        : "+f"(c[0]), "+f"(c[1]), "+f"(c[2]), "+f"(c[3])
        : "r"(a[0]), "r"(a[1]), "r"(a[2]), "r"(a[3]), "r"(b0), "r"(b1));
}
__device__ __forceinline__ void mma_fp8(float* c, const unsigned* a, unsigned b0, unsigned b1) {
    asm volatile(
        "mma.sync.aligned.m16n8k32.row.col.f32.e4m3.e4m3.f32 "
        "{%0,%1,%2,%3},{%4,%5,%6,%7},{%8,%9},{%0,%1,%2,%3};\n"
        : "+f"(c[0]), "+f"(c[1]), "+f"(c[2]), "+f"(c[3])
        : "r"(a[0]), "r"(a[1]), "r"(a[2]), "r"(a[3]), "r"(b0), "r"(b1));
}
__device__ __forceinline__ unsigned lds32(uint32_t addr) {
    unsigned v;
    asm volatile("ld.shared.b32 %0, [%1];" : "=r"(v) : "r"(addr));
    return v;
}
__device__ __forceinline__ float sigm(float x) { return 1.0f / (1.0f + __expf(-x)); }

// ---------------------------------------------------------------------------
// Mixed-precision split GEMM, tile 64(batch) x 128(32 j x 4 gates):
//   phase FP8 (chunks 0..KKc-1):  acc += 1024*(x_lo*w_hi + x_hi*w_lo)  [e4m3 k32]
//   scale: acc *= 1/1024
//   phase BF16 (chunks KKc..2KKc-1): acc += x_hi * w_hi               [bf16 k16]
// 8 warps = 2(m:32) x 4(j-slice of 8); in-register LSTM epilogue.
// 4-stage cp.async ring, stage = A(64x144B) + B(128x144B) = 27648B.
// ---------------------------------------------------------------------------
#define STG_BYTES 27648
#define B_OFF 9216
#define DYN_BYTES (4 * STG_BYTES)   // 110592

template <int K1, int K2, int HH, bool PRE>
__global__ __launch_bounds__(256, 2)
void gemm_kernel(const bf16* __restrict__ Ai_hi, const fp8* __restrict__ Ai_8h, const fp8* __restrict__ Ai_8l,
                 const bf16* __restrict__ Ah_hi, const fp8* __restrict__ Ah_8h, const fp8* __restrict__ Ah_8l,
                 const bf16* __restrict__ Wi_hi, const fp8* __restrict__ Wi_8h, const fp8* __restrict__ Wi_8l,
                 const bf16* __restrict__ Wh_hi, const fp8* __restrict__ Wh_8h, const fp8* __restrict__ Wh_8l,
                 const float* __restrict__ bih, const float* __restrict__ bhh,
                 const float* __restrict__ xpre,
                 float* __restrict__ c,
                 bf16* __restrict__ ho_hi, fp8* __restrict__ ho_8h, fp8* __restrict__ ho_8l,
                 float* __restrict__ gout)
{
    constexpr int KK = K1 + K2;
    constexpr int KKc = KK / 64;       // chunk count per phase
    constexpr int NCHT = 2 * KKc;

    extern __shared__ __align__(16) char dyn[];
    const uint32_t sbase = smem_u32(dyn);

    const int tid = threadIdx.x;
    const int wid = tid >> 5, lane = tid & 31;
    const int wm = wid >> 2, wn = wid & 3;
    const int j0 = blockIdx.x * 32;
    const int b0 = blockIdx.y * 64;

    float acc[2][4][4];
#pragma unroll
    for (int mi = 0; mi < 2; ++mi)
#pragma unroll
        for (int g = 0; g < 4; ++g)
#pragma unroll
            for (int r = 0; r < 4; ++r) acc[mi][g][r] = 0.0f;

    auto load_stage = [&](int ci, int s) {
        const uint32_t abase = sbase + (uint32_t)s * STG_BYTES;
        const uint32_t bbase = abase + B_OFF;
        if (ci < KKc) {
            // fp8 chunk: 128 fp8 k-elems. term 0: A=lo, W=hi(*4); term 1: A=hi(/4), W=lo
            const int kg8 = ci * 128;
            const int term = (kg8 >= KK) ? 1 : 0;
            const int kk8 = kg8 - term * KK;
            const fp8 *A8, *B8;
            int col, ld;
            if (kk8 < K1) {
                A8 = term ? Ai_8h : Ai_8l;
                B8 = term ? Wi_8l : Wi_8h;
                col = kk8; ld = K1;
            } else {
                A8 = term ? Ah_8h : Ah_8l;
                B8 = term ? Wh_8l : Wh_8h;
                col = kk8 - K1; ld = K2;
            }
#pragma unroll
            for (int it = 0; it < 2; ++it) {
                const int idx = tid + it * 256;
                const int r = idx >> 3, q = idx & 7;
                cp16(abase + (uint32_t)(r * 144 + q * 16),
                     A8 + (size_t)(b0 + r) * ld + col + q * 16);
            }
#pragma unroll
            for (int it = 0; it < 4; ++it) {
                const int idx = tid + it * 256;
                const int r = idx >> 3, q = idx & 7;
                const int gate = r >> 5, jl = r & 31;
                cp16(bbase + (uint32_t)(r * 144 + q * 16),
                     B8 + (size_t)(gate * HH + j0 + jl) * ld + col + q * 16);
            }
        } else {
            // bf16 chunk: 64 bf16 k-elems
            const int kk = (ci - KKc) * 64;
            const bf16 *A, *W;
            int col, ld;
            if (kk < K1) { A = Ai_hi; W = Wi_hi; col = kk;      ld = K1; }
            else         { A = Ah_hi; W = Wh_hi; col = kk - K1; ld = K2; }
#pragma unroll
            for (int it = 0; it < 2; ++it) {
                const int idx = tid + it * 256;
                const int r = idx >> 3, q = idx & 7;
                cp16(abase + (uint32_t)(r * 144 + q * 16),
                     A + (size_t)(b0 + r) * ld + col + q * 8);
            }
#pragma unroll
            for (int it = 0; it < 4; ++it) {
                const int idx = tid + it * 256;
                const int r = idx >> 3, q = idx & 7;
                const int gate = r >> 5, jl = r & 31;
                cp16(bbase + (uint32_t)(r * 144 + q * 16),
                     W + (size_t)(gate * HH + j0 + jl) * ld + col + q * 8);
            }
        }
        CP_COMMIT();
    };

    // fragment addressing
    const int arow = lane & 15;
    const int acol16 = (lane >> 4) << 4;           // byte offset (16B halves)
    const int b_gsel = (lane >> 3) & 1;            // bf16 b-gather
    const int b_kadd = (lane >> 4) << 3;           // b16 units
    const int b_jrow = wn * 8 + (lane & 7);
    const int b8_row = wn * 8 + (lane >> 2);       // fp8 b: n = lane>>2
    const int b8_col = (lane & 3) << 2;            // fp8 b: 4 bytes at k

    auto compute_fp8 = [&](int s) {
        const uint32_t abase = sbase + (uint32_t)s * STG_BYTES;
        const uint32_t bbase = abase + B_OFF;
#pragma unroll
        for (int kh = 0; kh < 4; ++kh) {
            const int kcB = kh * 32;
            unsigned a8[2][4], b8[4][2];
#pragma unroll
            for (int g = 0; g < 4; ++g) {
                const uint32_t ba = bbase + (uint32_t)((g * 32 + b8_row) * 144 + kcB + b8_col);
                b8[g][0] = lds32(ba);
                b8[g][1] = lds32(ba + 16);
            }
#pragma unroll
            for (int mi = 0; mi < 2; ++mi) {
                const int row = wm * 32 + mi * 16 + arow;
                ldsm4(a8[mi], abase + (uint32_t)(row * 144 + kcB + acol16));
            }
#pragma unroll
            for (int mi = 0; mi < 2; ++mi)
#pragma unroll
                for (int g = 0; g < 4; ++g)
                    mma_fp8(acc[mi][g], a8[mi], b8[g][0], b8[g][1]);
        }
    };

    auto compute_f16 = [&](int s) {
        const uint32_t abase = sbase + (uint32_t)s * STG_BYTES;
        const uint32_t bbase = abase + B_OFF;
#pragma unroll
        for (int kh = 0; kh < 4; ++kh) {
            const int kc = kh * 16;                 // b16 units
            unsigned a0[2][4], bA[4], bB[4];
            ldsm4(bA, bbase + (uint32_t)(((b_gsel * 32 + b_jrow) * 72 + kc + b_kadd) * 2));
            ldsm4(bB, bbase + (uint32_t)((((2 + b_gsel) * 32 + b_jrow) * 72 + kc + b_kadd) * 2));
#pragma unroll
            for (int mi = 0; mi < 2; ++mi) {
                const int row = wm * 32 + mi * 16 + arow;
                ldsm4(a0[mi], abase + (uint32_t)((row * 72 + kc + ((lane >> 4) << 3)) * 2));
            }
#pragma unroll
            for (int mi = 0; mi < 2; ++mi) {
                mma_bf16(acc[mi][0], a0[mi], bA[0], bA[2]);
                mma_bf16(acc[mi][1], a0[mi], bA[1], bA[3]);
                mma_bf16(acc[mi][2], a0[mi], bB[0], bB[2]);
                mma_bf16(acc[mi][3], a0[mi], bB[1], bB[3]);
            }
        }
    };

    load_stage(0, 0);
    load_stage(1, 1);
    load_stage(2, 2);

    for (int ci = 0; ci < NCHT; ++ci) {
        const int rem = NCHT - 1 - ci;
        if (rem >= 2)      { CP_WAIT(2); }
        else if (rem == 1) { CP_WAIT(1); }
        else               { CP_WAIT(0); }
        __syncthreads();
        if (ci + 3 < NCHT) load_stage(ci + 3, (ci + 3) & 3);
        if (ci < KKc) {
            compute_fp8(ci & 3);
            if (ci == KKc - 1) {
#pragma unroll
                for (int mi = 0; mi < 2; ++mi)
#pragma unroll
                    for (int g = 0; g < 4; ++g)
#pragma unroll
                        for (int r = 0; r < 4; ++r) acc[mi][g][r] *= INV_S;
            }
        } else {
            compute_f16(ci & 3);
        }
    }

    // ---------------- in-register epilogue ----------------
    const int g4 = lane >> 2, tg = lane & 3;
    const int j = j0 + wn * 8 + tg * 2;

    if (PRE) {
#pragma unroll
        for (int mi = 0; mi < 2; ++mi)
#pragma unroll
            for (int rh = 0; rh < 2; ++rh) {
                const int b = b0 + wm * 32 + mi * 16 + g4 + rh * 8;
                float* orow = gout + (size_t)b * (4 * HH) + j;
#pragma unroll
                for (int g = 0; g < 4; ++g) {
                    float2 v = make_float2(acc[mi][g][rh * 2], acc[mi][g][rh * 2 + 1]);
                    *reinterpret_cast<float2*>(orow + g * HH) = v;
                }
            }
    } else {
        float2 bsum[4];
#pragma unroll
        for (int g = 0; g < 4; ++g) {
            const float2 bi = *reinterpret_cast<const float2*>(bih + g * HH + j);
            const float2 bh = *reinterpret_cast<const float2*>(bhh + g * HH + j);
            bsum[g] = make_float2(bi.x + bh.x, bi.y + bh.y);
        }
#pragma unroll
        for (int mi = 0; mi < 2; ++mi)
#pragma unroll
            for (int rh = 0; rh < 2; ++rh) {
                const int b = b0 + wm * 32 + mi * 16 + g4 + rh * 8;
                float2 gv[4];
#pragma unroll
                for (int g = 0; g < 4; ++g)
                    gv[g] = make_float2(acc[mi][g][rh * 2] + bsum[g].x,
                                        acc[mi][g][rh * 2 + 1] + bsum[g].y);
                if (xpre) {
                    const float* xr = xpre + (size_t)b * (4 * HH) + j;
#pragma unroll
                    for (int g = 0; g < 4; ++g) {
                        const float2 xv = *reinterpret_cast<const float2*>(xr + g * HH);
                        gv[g].x += xv.x; gv[g].y += xv.y;
                    }
                }
                const size_t off = (size_t)b * HH + j;
                const float2 cv = *reinterpret_cast<const float2*>(c + off);

                const float i0 = sigm(gv[0].x), i1 = sigm(gv[0].y);
                const float f0 = sigm(gv[1].x), f1 = sigm(gv[1].y);
                const float g0 = tanhf(gv[2].x), g1 = tanhf(gv[2].y);
                const float o0 = sigm(gv[3].x), o1 = sigm(gv[3].y);
                const float cn0 = f0 * cv.x + i0 * g0;
                const float cn1 = f1 * cv.y + i1 * g1;
                *reinterpret_cast<float2*>(c + off) = make_float2(cn0, cn1);
                const float hn0 = o0 * tanhf(cn0);
                const float hn1 = o1 * tanhf(cn1);
                const bf16 h0 = __float2bfloat16(hn0);
                const bf16 h1 = __float2bfloat16(hn1);
                *reinterpret_cast<__nv_bfloat162*>(ho_hi + off) = __nv_bfloat162(h0, h1);
                fp8 p0(hn0 * 0.25f), p1(hn1 * 0.25f);
                fp8 q0((hn0 - __bfloat162float(h0)) * 256.0f);
                fp8 q1((hn1 - __bfloat162float(h1)) * 256.0f);
                *reinterpret_cast<uchar2*>(ho_8h + off) = make_uchar2(p0.__x, p1.__x);
                *reinterpret_cast<uchar2*>(ho_8l + off) = make_uchar2(q0.__x, q1.__x);
            }
    }
}

// ---------------- prep / init / finalize ------------------------------------
__global__ void split_kernel(const float* __restrict__ src, bf16* __restrict__ hi,
                             fp8* __restrict__ q8h, fp8* __restrict__ q8l,
                             int n, float sh, float sl) {
    int i = blockIdx.x * blockDim.x + threadIdx.x;
    const int st = gridDim.x * blockDim.x;
    for (; i < n; i += st) {
        const float v = src[i];
        const bf16 h = __float2bfloat16(v);
        hi[i] = h;
        q8h[i] = fp8(v * sh);
        q8l[i] = fp8((v - __bfloat162float(h)) * sl);
    }
}

__global__ void init_state_kernel() {
    int idx = blockIdx.x * blockDim.x + threadIdx.x;
    const int st = gridDim.x * blockDim.x;
    const int N1 = BB * H1, N3 = BB * H3;
    const bf16 z = __float2bfloat16(0.0f);
    fp8 z8(0.0f);
    for (int i = idx; i < N1; i += st) {
        g_h1_hi[0][i] = z; g_h1_hi[1][i] = z;
        g_h1_8h[0][i] = z8; g_h1_8h[1][i] = z8;
        g_h1_8l[0][i] = z8; g_h1_8l[1][i] = z8;
        g_h2_hi[0][i] = z; g_h2_hi[1][i] = z;
        g_h2_8h[0][i] = z8; g_h2_8h[1][i] = z8;
        g_h2_8l[0][i] = z8; g_h2_8l[1][i] = z8;
        g_c1[i] = 0.f; g_c2[i] = 0.f;
    }
    for (int i = idx; i < N3; i += st) {
        g_h3_hi[0][i] = z; g_h3_hi[1][i] = z;
        g_h3_8h[0][i] = z8; g_h3_8h[1][i] = z8;
        g_h3_8l[0][i] = z8; g_h3_8l[1][i] = z8;
        g_c3[i] = 0.f;
    }
}

__global__ void finalize_kernel(float* __restrict__ out) {
    int idx = blockIdx.x * blockDim.x + threadIdx.x;
    const int st = gridDim.x * blockDim.x;
    const int N1 = BB * H1, N3 = BB * H3;
    for (int i = idx; i < N1; i += st) {
        out[0 * N1 + i] = __bfloat162float(g_h1_hi[0][i]) + float(g_h1_8l[0][i]) * (1.0f / 256.0f);
        out[1 * N1 + i] = g_c1[i];
        out[2 * N1 + i] = __bfloat162float(g_h2_hi[0][i]) + float(g_h2_8l[0][i]) * (1.0f / 256.0f);
        out[3 * N1 + i] = g_c2[i];
    }
    for (int i = idx; i < N3; i += st) {
        out[4 * N1 + i] = __bfloat162float(g_h3_hi[0][i]) + float(g_h3_8l[0][i]) * (1.0f / 256.0f);
        out[4 * N1 + N3 + i] = g_c3[i];
    }
}

// ---------------- launch ----------------------------------------------------
extern "C" void kernel_launch(void* const* d_in, const int* in_sizes, int n_in,
                              void* d_out, int out_size) {
    const float* x    = (const float*)d_in[0];
    const float* Wih1 = (const float*)d_in[1];
    const float* Whh1 = (const float*)d_in[2];
    const float* bih1 = (const float*)d_in[3];
    const float* bhh1 = (const float*)d_in[4];
    const float* Wih2 = (const float*)d_in[5];
    const float* Whh2 = (const float*)d_in[6];
    const float* bih2 = (const float*)d_in[7];
    const float* bhh2 = (const float*)d_in[8];
    const float* Wih3 = (const float*)d_in[9];
    const float* Whh3 = (const float*)d_in[10];
    const float* bih3 = (const float*)d_in[11];
    const float* bhh3 = (const float*)d_in[12];
    float* out = (float*)d_out;

    bf16 *x_hi; fp8 *x_8h, *x_8l; float* xpre;
    bf16 *W1i, *W1h, *W2i, *W2h, *W3i, *W3h;
    fp8 *W1i8h, *W1i8l, *W1h8h, *W1h8l, *W2i8h, *W2i8l, *W2h8h, *W2h8l, *W3i8h, *W3i8l, *W3h8h, *W3h8l;
    bf16 *h1, *h2, *h3; fp8 *h18h, *h18l, *h28h, *h28l, *h38h, *h38l;
    float *c1, *c2, *c3;

    cudaGetSymbolAddress((void**)&x_hi, g_x_hi);
    cudaGetSymbolAddress((void**)&x_8h, g_x_8h);
    cudaGetSymbolAddress((void**)&x_8l, g_x_8l);
    cudaGetSymbolAddress((void**)&xpre, g_xpre);
    cudaGetSymbolAddress((void**)&W1i, g_W1i_hi);
    cudaGetSymbolAddress((void**)&W1i8h, g_W1i_8h);
    cudaGetSymbolAddress((void**)&W1i8l, g_W1i_8l);
    cudaGetSymbolAddress((void**)&W1h, g_W1h_hi);
    cudaGetSymbolAddress((void**)&W1h8h, g_W1h_8h);
    cudaGetSymbolAddress((void**)&W1h8l, g_W1h_8l);
    cudaGetSymbolAddress((void**)&W2i, g_W2i_hi);
    cudaGetSymbolAddress((void**)&W2i8h, g_W2i_8h);
    cudaGetSymbolAddress((void**)&W2i8l, g_W2i_8l);
    cudaGetSymbolAddress((void**)&W2h, g_W2h_hi);
    cudaGetSymbolAddress((void**)&W2h8h, g_W2h_8h);
    cudaGetSymbolAddress((void**)&W2h8l, g_W2h_8l);
    cudaGetSymbolAddress((void**)&W3i, g_W3i_hi);
    cudaGetSymbolAddress((void**)&W3i8h, g_W3i_8h);
    cudaGetSymbolAddress((void**)&W3i8l, g_W3i_8l);
    cudaGetSymbolAddress((void**)&W3h, g_W3h_hi);
    cudaGetSymbolAddress((void**)&W3h8h, g_W3h_8h);
    cudaGetSymbolAddress((void**)&W3h8l, g_W3h_8l);
    cudaGetSymbolAddress((void**)&h1, g_h1_hi);
    cudaGetSymbolAddress((void**)&h18h, g_h1_8h);
    cudaGetSymbolAddress((void**)&h18l, g_h1_8l);
    cudaGetSymbolAddress((void**)&h2, g_h2_hi);
    cudaGetSymbolAddress((void**)&h28h, g_h2_8h);
    cudaGetSymbolAddress((void**)&h28l, g_h2_8l);
    cudaGetSymbolAddress((void**)&h3, g_h3_hi);
    cudaGetSymbolAddress((void**)&h38h, g_h3_8h);
    cudaGetSymbolAddress((void**)&h38l, g_h3_8l);
    cudaGetSymbolAddress((void**)&c1, g_c1);
    cudaGetSymbolAddress((void**)&c2, g_c2);
    cudaGetSymbolAddress((void**)&c3, g_c3);

    cudaFuncSetAttribute(gemm_kernel<DIN, 0, H1, true>,
                         cudaFuncAttributeMaxDynamicSharedMemorySize, DYN_BYTES);
    cudaFuncSetAttribute(gemm_kernel<H1, 0, H1, false>,
                         cudaFuncAttributeMaxDynamicSharedMemorySize, DYN_BYTES);
    cudaFuncSetAttribute(gemm_kernel<H1, H2, H2, false>,
                         cudaFuncAttributeMaxDynamicSharedMemorySize, DYN_BYTES);
    cudaFuncSetAttribute(gemm_kernel<H2, H3, H3, false>,
                         cudaFuncAttributeMaxDynamicSharedMemorySize, DYN_BYTES);

    static cudaStream_t s1 = nullptr, s2 = nullptr, s3 = nullptr;
    static cudaEvent_t ev1r[4], ev2r[4], ev3r[4], evFork, evJ1, evJ2, evJ3;
    if (!s1) {
        cudaStreamCreateWithFlags(&s1, cudaStreamNonBlocking);
        cudaStreamCreateWithFlags(&s2, cudaStreamNonBlocking);
        cudaStreamCreateWithFlags(&s3, cudaStreamNonBlocking);
        for (int i = 0; i < 4; ++i) {
            cudaEventCreateWithFlags(&ev1r[i], cudaEventDisableTiming);
            cudaEventCreateWithFlags(&ev2r[i], cudaEventDisableTiming);
            cudaEventCreateWithFlags(&ev3r[i], cudaEventDisableTiming);
        }
        cudaEventCreateWithFlags(&evFork, cudaEventDisableTiming);
        cudaEventCreateWithFlags(&evJ1, cudaEventDisableTiming);
        cudaEventCreateWithFlags(&evJ2, cudaEventDisableTiming);
        cudaEventCreateWithFlags(&evJ3, cudaEventDisableTiming);
    }

    // -------- prologue (legacy stream) --------
    split_kernel<<<2048, 256>>>(x, x_hi, x_8h, x_8l, TT * BB * DIN, 0.25f, 256.0f);
    split_kernel<<<1024, 256>>>(Wih1, W1i, W1i8h, W1i8l, 4 * H1 * DIN, 4.0f, 4096.0f);
    split_kernel<<<1024, 256>>>(Whh1, W1h, W1h8h, W1h8l, 4 * H1 * H1, 4.0f, 4096.0f);
    split_kernel<<<1024, 256>>>(Wih2, W2i, W2i8h, W2i8l, 4 * H2 * H1, 4.0f, 4096.0f);
    split_kernel<<<1024, 256>>>(Whh2, W2h, W2h8h, W2h8l, 4 * H2 * H2, 4.0f, 4096.0f);
    split_kernel<<<1024, 256>>>(Wih3, W3i, W3i8h, W3i8l, 4 * H3 * H2, 4.0f, 4096.0f);
    split_kernel<<<1024, 256>>>(Whh3, W3h, W3h8h, W3h8l, 4 * H3 * H3, 4.0f, 4096.0f);
    init_state_kernel<<<512, 256>>>();

    // big precompute: X1 = x @ Wih1^T for all T*B rows
    gemm_kernel<DIN, 0, H1, true><<<dim3(H1 / 32, TT * BB / 64), 256, DYN_BYTES>>>(
        x_hi, x_8h, x_8l, nullptr, nullptr, nullptr,
        W1i, W1i8h, W1i8l, nullptr, nullptr, nullptr,
        nullptr, nullptr, nullptr, nullptr, nullptr, nullptr, nullptr, xpre);

    cudaEventRecord(evFork, 0);
    cudaStreamWaitEvent(s1, evFork, 0);
    cudaStreamWaitEvent(s2, evFork, 0);
    cudaStreamWaitEvent(s3, evFork, 0);

    const int N1 = BB * H1, N2 = BB * H2, N3 = BB * H3;

    for (int t = 0; t < TT; ++t) {
        const int pi = t & 1, po = (t + 1) & 1;

        if (t >= 2) cudaStreamWaitEvent(s1, ev2r[(t - 2) & 3], 0);
        gemm_kernel<H1, 0, H1, false><<<dim3(H1 / 32, BB / 64), 256, DYN_BYTES, s1>>>(
            h1 + pi * N1, h18h + pi * N1, h18l + pi * N1, nullptr, nullptr, nullptr,
            W1h, W1h8h, W1h8l, nullptr, nullptr, nullptr,
            bih1, bhh1, xpre + (size_t)t * BB * 4 * H1,
            c1, h1 + po * N1, h18h + po * N1, h18l + po * N1, nullptr);
        cudaEventRecord(ev1r[t & 3], s1);

        cudaStreamWaitEvent(s2, ev1r[t & 3], 0);
        if (t >= 2) cudaStreamWaitEvent(s2, ev3r[(t - 2) & 3], 0);
        gemm_kernel<H1, H2, H2, false><<<dim3(H2 / 32, BB / 64), 256, DYN_BYTES, s2>>>(
            h1 + po * N1, h18h + po * N1, h18l + po * N1,
            h2 + pi * N2, h28h + pi * N2, h28l + pi * N2,
            W2i, W2i8h, W2i8l, W2h, W2h8h, W2h8l,
            bih2, bhh2, nullptr,
            c2, h2 + po * N2, h28h + po * N2, h28l + po * N2, nullptr);
        cudaEventRecord(ev2r[t & 3], s2);

        cudaStreamWaitEvent(s3, ev2r[t & 3], 0);
        gemm_kernel<H2, H3, H3, false><<<dim3(H3 / 32, BB / 64), 256, DYN_BYTES, s3>>>(
            h2 + po * N2, h28h + po * N2, h28l + po * N2,
            h3 + pi * N3, h38h + pi * N3, h38l + pi * N3,
            W3i, W3i8h, W3i8l, W3h, W3h8h, W3h8l,
            bih3, bhh3, nullptr,
            c3, h3 + po * N3, h38h + po * N3, h38l + po * N3, nullptr);
        cudaEventRecord(ev3r[t & 3], s3);
    }

    cudaEventRecord(evJ1, s1);
    cudaEventRecord(evJ2, s2);
    cudaEventRecord(evJ3, s3);
    cudaStreamWaitEvent(0, evJ1, 0);
    cudaStreamWaitEvent(0, evJ2, 0);
    cudaStreamWaitEvent(0, evJ3, 0);

    finalize_kernel<<<256, 256>>>(out);
}